// round 1
// baseline (speedup 1.0000x reference)
#include <cuda_runtime.h>
#include <cuda_fp16.h>
#include <math.h>
#include <stdint.h>

#define MT   16384      // tokens = 4 * 4096
#define D    1024
#define DFF  4096
#define S_LEN 4096

// ---------------- scratch (static __device__ allocations; ~400 MB) ----------------
__device__ __half g_h   [(size_t)MT * D];        // LN1 output (fp16)
__device__ __half g_Wgv [(size_t)2 * D * D];     // packed [gate_w ; val_w]  [2048,1024] fp16
__device__ __half g_W1  [(size_t)DFF * D];       // ffn1_w fp16
__device__ __half g_W2  [(size_t)D * DFF];       // ffn2_w fp16
__device__ __half g_lin [(size_t)MT * 2 * D];    // gate/val linear out fp16
__device__ __half g_gbuf[(size_t)MT * D];        // g = sigmoid(...)
__device__ __half g_gvbuf[(size_t)MT * D];       // g * v
__device__ float  g_xmid[(size_t)MT * D];        // x + mem (fp32, residual source)
__device__ __half g_h2  [(size_t)MT * D];        // LN2 output fp16
__device__ __half g_a1  [(size_t)MT * DFF];      // gelu(ffn1) fp16

// ---------------- small asm helpers ----------------
__device__ __forceinline__ uint32_t smem_u32(const void* p) {
    return (uint32_t)__cvta_generic_to_shared(p);
}
__device__ __forceinline__ void cp16(uint32_t dst, const void* src) {
    asm volatile("cp.async.cg.shared.global [%0], [%1], 16;\n" :: "r"(dst), "l"(src) : "memory");
}
__device__ __forceinline__ void cp_commit() {
    asm volatile("cp.async.commit_group;\n" ::: "memory");
}
__device__ __forceinline__ void cp_wait1() {
    asm volatile("cp.async.wait_group 1;\n" ::: "memory");
}
__device__ __forceinline__ void cp_wait0() {
    asm volatile("cp.async.wait_group 0;\n" ::: "memory");
}
__device__ __forceinline__ void ldsm4(uint32_t& r0, uint32_t& r1, uint32_t& r2, uint32_t& r3, uint32_t a) {
    asm volatile("ldmatrix.sync.aligned.m8n8.x4.shared.b16 {%0,%1,%2,%3}, [%4];\n"
                 : "=r"(r0), "=r"(r1), "=r"(r2), "=r"(r3) : "r"(a));
}
__device__ __forceinline__ void mma16816(float c[4],
                                         uint32_t a0, uint32_t a1, uint32_t a2, uint32_t a3,
                                         uint32_t b0, uint32_t b1) {
    asm volatile("mma.sync.aligned.m16n8k16.row.col.f32.f16.f16.f32 "
                 "{%0,%1,%2,%3},{%4,%5,%6,%7},{%8,%9},{%0,%1,%2,%3};\n"
                 : "+f"(c[0]), "+f"(c[1]), "+f"(c[2]), "+f"(c[3])
                 : "r"(a0), "r"(a1), "r"(a2), "r"(a3), "r"(b0), "r"(b1));
}
__device__ __forceinline__ float gelu_f(float x) {
    return 0.5f * x * (1.0f + erff(x * 0.70710678118654752f));  // exact gelu
}

// ---------------- weight fp32 -> fp16 ----------------
__global__ void cvt_kernel(const float* __restrict__ src, __half* __restrict__ dst, int n4) {
    int i = blockIdx.x * blockDim.x + threadIdx.x;
    if (i >= n4) return;
    float4 v = ((const float4*)src)[i];
    ((__half2*)dst)[2 * i]     = __floats2half2_rn(v.x, v.y);
    ((__half2*)dst)[2 * i + 1] = __floats2half2_rn(v.z, v.w);
}

// ---------------- layernorm: one warp per row of 1024 ----------------
__global__ void __launch_bounds__(256) ln_kernel(const float* __restrict__ in,
                                                 const float* __restrict__ w,
                                                 const float* __restrict__ b,
                                                 __half* __restrict__ out) {
    int row  = blockIdx.x * 8 + (threadIdx.x >> 5);
    int lane = threadIdx.x & 31;
    const float4* p = (const float4*)(in + (size_t)row * D);
    float4 v[8];
    float s = 0.f, sq = 0.f;
#pragma unroll
    for (int i = 0; i < 8; ++i) {
        v[i] = p[lane + i * 32];
        s  += v[i].x + v[i].y + v[i].z + v[i].w;
        sq += v[i].x * v[i].x + v[i].y * v[i].y + v[i].z * v[i].z + v[i].w * v[i].w;
    }
#pragma unroll
    for (int o = 16; o > 0; o >>= 1) {
        s  += __shfl_xor_sync(0xffffffffu, s, o);
        sq += __shfl_xor_sync(0xffffffffu, sq, o);
    }
    float mean = s * (1.0f / D);
    float inv  = rsqrtf(sq * (1.0f / D) - mean * mean + 1e-5f);
    __half2* o2 = (__half2*)(out + (size_t)row * D);
#pragma unroll
    for (int i = 0; i < 8; ++i) {
        int c4 = lane + i * 32;
        float4 wv = ((const float4*)w)[c4];
        float4 bv = ((const float4*)b)[c4];
        float y0 = (v[i].x - mean) * inv * wv.x + bv.x;
        float y1 = (v[i].y - mean) * inv * wv.y + bv.y;
        float y2 = (v[i].z - mean) * inv * wv.z + bv.z;
        float y3 = (v[i].w - mean) * inv * wv.w + bv.w;
        o2[c4 * 2]     = __floats2half2_rn(y0, y1);
        o2[c4 * 2 + 1] = __floats2half2_rn(y2, y3);
    }
}

// ---------------- g = sigmoid(gate+gb), gv = g*(val+vb) ----------------
__global__ void sigmul_kernel(const float* __restrict__ gate_b, const float* __restrict__ val_b) {
    int i  = blockIdx.x * blockDim.x + threadIdx.x;   // MT*512 threads (half2 granularity)
    int m  = i >> 9;
    int c2 = i & 511;
    const __half2* lin2 = (const __half2*)g_lin;      // row stride 1024 half2 (=2048 halves)
    float2 gl = __half22float2(lin2[(size_t)m * 1024 + c2]);
    float2 vl = __half22float2(lin2[(size_t)m * 1024 + 512 + c2]);
    float2 gb = ((const float2*)gate_b)[c2];
    float2 vb = ((const float2*)val_b)[c2];
    float g0 = 1.0f / (1.0f + expf(-(gl.x + gb.x)));
    float g1 = 1.0f / (1.0f + expf(-(gl.y + gb.y)));
    float v0 = vl.x + vb.x, v1 = vl.y + vb.y;
    ((__half2*)g_gbuf)[i]  = __floats2half2_rn(g0, g1);
    ((__half2*)g_gvbuf)[i] = __floats2half2_rn(g0 * v0, g1 * v1);
}

// ---------------- cumsum along S + memory term + residual ----------------
__global__ void __launch_bounds__(128) cumsum_kernel(const float* __restrict__ x,
                                                     float* __restrict__ xmid) {
    int d = blockIdx.x * 128 + threadIdx.x;
    size_t base = (size_t)blockIdx.y * S_LEN * D + d;
    float ag = 0.f, av = 0.f;
#pragma unroll 4
    for (int s = 0; s < S_LEN; ++s) {
        size_t idx = base + (size_t)s * D;
        ag += __half2float(g_gbuf[idx]);
        av += __half2float(g_gvbuf[idx]);
        float scale = rsqrtf((ag + 1e-6f) * ((float)(s + 1) * (1.0f / S_LEN) + 0.1f));
        xmid[idx] = x[idx] + av * scale;
    }
}

// ---------------- fp16 GEMM: C[M,N] = A[M,K] * B[N,K]^T, fp32 accum ----------------
// EPI 0: store fp16 (raw linear)        -> outH
// EPI 1: gelu(acc + bias)   fp16        -> outH
// EPI 2: acc + bias + resid fp32        -> outF
template <int EPI>
__global__ void __launch_bounds__(256) gemm_kernel(const __half* __restrict__ A,
                                                   const __half* __restrict__ B,
                                                   int M, int N, int K,
                                                   const float* __restrict__ bias,
                                                   const float* __restrict__ resid,
                                                   __half* __restrict__ outH,
                                                   float* __restrict__ outF) {
    __shared__ __align__(16) __half sA[2][128][40];   // 80B row stride: conflict-free ldmatrix
    __shared__ __align__(16) __half sB[2][128][40];

    const int tid  = threadIdx.x;
    const int lane = tid & 31;
    const int warp = tid >> 5;
    const int m0 = (warp >> 2) * 64;   // warp tile 64x32, warps 2x4
    const int n0 = (warp & 3) * 32;
    const int bm = blockIdx.y * 128;
    const int bn = blockIdx.x * 128;

    const int lrow = tid >> 2;          // 0..63
    const int lcol = (tid & 3) * 8;     // 0,8,16,24 halves
    const __half* gA = A + (size_t)(bm + lrow) * K + lcol;
    const __half* gB = B + (size_t)(bn + lrow) * K + lcol;
    const uint32_t sA0 = smem_u32(&sA[0][lrow][lcol]);
    const uint32_t sB0 = smem_u32(&sB[0][lrow][lcol]);
    const uint32_t bufStride = 128 * 40 * 2;  // bytes per buffer

    float acc[4][4][4];
#pragma unroll
    for (int i = 0; i < 4; ++i)
#pragma unroll
        for (int j = 0; j < 4; ++j)
#pragma unroll
            for (int q = 0; q < 4; ++q) acc[i][j][q] = 0.f;

    const int KT = K >> 5;

    // preload k-tile 0 into buffer 0
    {
        cp16(sA0,                 gA);
        cp16(sA0 + 64 * 80,       gA + (size_t)64 * K);
        cp16(sB0,                 gB);
        cp16(sB0 + 64 * 80,       gB + (size_t)64 * K);
        cp_commit();
    }

    for (int kt = 0; kt < KT; ++kt) {
        const int buf = kt & 1;
        if (kt + 1 < KT) {
            const int k0 = (kt + 1) * 32;
            const uint32_t da = sA0 + (buf ^ 1) * bufStride;
            const uint32_t db = sB0 + (buf ^ 1) * bufStride;
            cp16(da,           gA + k0);
            cp16(da + 64 * 80, gA + (size_t)64 * K + k0);
            cp16(db,           gB + k0);
            cp16(db + 64 * 80, gB + (size_t)64 * K + k0);
            cp_commit();
            cp_wait1();
        } else {
            cp_wait0();
        }
        __syncthreads();

#pragma unroll
        for (int kk = 0; kk < 2; ++kk) {
            uint32_t a[4][4], bf[4][2];
#pragma unroll
            for (int mi = 0; mi < 4; ++mi) {
                int r = m0 + mi * 16 + (lane & 15);
                int c = kk * 16 + ((lane >> 4) << 3);
                ldsm4(a[mi][0], a[mi][1], a[mi][2], a[mi][3], smem_u32(&sA[buf][r][c]));
            }
#pragma unroll
            for (int gi = 0; gi < 2; ++gi) {
                int r = n0 + gi * 16 + ((lane >> 4) & 1) * 8 + (lane & 7);
                int c = kk * 16 + ((lane >> 3) & 1) * 8;
                ldsm4(bf[2 * gi][0], bf[2 * gi][1], bf[2 * gi + 1][0], bf[2 * gi + 1][1],
                      smem_u32(&sB[buf][r][c]));
            }
#pragma unroll
            for (int mi = 0; mi < 4; ++mi)
#pragma unroll
                for (int ni = 0; ni < 4; ++ni)
                    mma16816(acc[mi][ni], a[mi][0], a[mi][1], a[mi][2], a[mi][3],
                             bf[ni][0], bf[ni][1]);
        }
        __syncthreads();
    }

    // epilogue
#pragma unroll
    for (int mi = 0; mi < 4; ++mi) {
#pragma unroll
        for (int ni = 0; ni < 4; ++ni) {
            int row = bm + m0 + mi * 16 + (lane >> 2);
            int col = bn + n0 + ni * 8 + (lane & 3) * 2;
            float* ap = acc[mi][ni];
            if (EPI == 0) {
                *(__half2*)(outH + (size_t)row * N + col)       = __floats2half2_rn(ap[0], ap[1]);
                *(__half2*)(outH + (size_t)(row + 8) * N + col) = __floats2half2_rn(ap[2], ap[3]);
            } else if (EPI == 1) {
                float b0 = bias[col], b1 = bias[col + 1];
                *(__half2*)(outH + (size_t)row * N + col) =
                    __floats2half2_rn(gelu_f(ap[0] + b0), gelu_f(ap[1] + b1));
                *(__half2*)(outH + (size_t)(row + 8) * N + col) =
                    __floats2half2_rn(gelu_f(ap[2] + b0), gelu_f(ap[3] + b1));
            } else {
                float b0 = bias[col], b1 = bias[col + 1];
                float2 r0 = *(const float2*)(resid + (size_t)row * N + col);
                float2 r1 = *(const float2*)(resid + (size_t)(row + 8) * N + col);
                float2 o0 = make_float2(ap[0] + b0 + r0.x, ap[1] + b1 + r0.y);
                float2 o1 = make_float2(ap[2] + b0 + r1.x, ap[3] + b1 + r1.y);
                *(float2*)(outF + (size_t)row * N + col)       = o0;
                *(float2*)(outF + (size_t)(row + 8) * N + col) = o1;
            }
        }
    }
}

// ---------------- launch ----------------
extern "C" void kernel_launch(void* const* d_in, const int* in_sizes, int n_in,
                              void* d_out, int out_size) {
    const float* x      = (const float*)d_in[0];
    const float* ln1_w  = (const float*)d_in[1];
    const float* ln1_b  = (const float*)d_in[2];
    const float* ln2_w  = (const float*)d_in[3];
    const float* ln2_b  = (const float*)d_in[4];
    const float* gate_w = (const float*)d_in[5];
    const float* gate_b = (const float*)d_in[6];
    const float* val_w  = (const float*)d_in[7];
    const float* val_b  = (const float*)d_in[8];
    const float* ffn1_w = (const float*)d_in[9];
    const float* ffn1_b = (const float*)d_in[10];
    const float* ffn2_w = (const float*)d_in[11];
    const float* ffn2_b = (const float*)d_in[12];
    float* out = (float*)d_out;

    void *pH, *pWgv, *pW1, *pW2, *pLin, *pXmid, *pH2, *pA1;
    cudaGetSymbolAddress(&pH,    g_h);
    cudaGetSymbolAddress(&pWgv,  g_Wgv);
    cudaGetSymbolAddress(&pW1,   g_W1);
    cudaGetSymbolAddress(&pW2,   g_W2);
    cudaGetSymbolAddress(&pLin,  g_lin);
    cudaGetSymbolAddress(&pXmid, g_xmid);
    cudaGetSymbolAddress(&pH2,   g_h2);
    cudaGetSymbolAddress(&pA1,   g_a1);

    // 1. weights fp32 -> fp16 (packed gate;val)
    int n4a = D * D / 4;
    cvt_kernel<<<(n4a + 255) / 256, 256>>>(gate_w, (__half*)pWgv, n4a);
    cvt_kernel<<<(n4a + 255) / 256, 256>>>(val_w, (__half*)pWgv + (size_t)D * D, n4a);
    int n4f = DFF * D / 4;
    cvt_kernel<<<(n4f + 255) / 256, 256>>>(ffn1_w, (__half*)pW1, n4f);
    cvt_kernel<<<(n4f + 255) / 256, 256>>>(ffn2_w, (__half*)pW2, n4f);

    // 2. LN1
    ln_kernel<<<MT / 8, 256>>>(x, ln1_w, ln1_b, (__half*)pH);

    // 3. fused gate+val GEMM: [MT,1024] x [2048,1024]^T -> lin fp16
    gemm_kernel<0><<<dim3(2 * D / 128, MT / 128), 256>>>(
        (const __half*)pH, (const __half*)pWgv, MT, 2 * D, D, nullptr, nullptr,
        (__half*)pLin, nullptr);

    // 4. sigmoid / gate*val
    sigmul_kernel<<<MT * 512 / 256, 256>>>(gate_b, val_b);

    // 5. cumsum + memory + residual -> xmid (fp32)
    cumsum_kernel<<<dim3(D / 128, 4), 128>>>(x, (float*)pXmid);

    // 6. LN2
    ln_kernel<<<MT / 8, 256>>>((const float*)pXmid, ln2_w, ln2_b, (__half*)pH2);

    // 7. FFN1 + exact gelu: [MT,1024] x [4096,1024]^T -> a1 fp16
    gemm_kernel<1><<<dim3(DFF / 128, MT / 128), 256>>>(
        (const __half*)pH2, (const __half*)pW1, MT, DFF, D, ffn1_b, nullptr,
        (__half*)pA1, nullptr);

    // 8. FFN2 + bias + residual: [MT,4096] x [1024,4096]^T -> out fp32
    gemm_kernel<2><<<dim3(D / 128, MT / 128), 256>>>(
        (const __half*)pA1, (const __half*)pW2, MT, D, DFF, ffn2_b, (const float*)pXmid,
        nullptr, out);
}

// round 3
// speedup vs baseline: 3.6293x; 3.6293x over previous
#include <cuda_runtime.h>
#include <cuda_fp16.h>
#include <math.h>
#include <stdint.h>

#define MT    16384
#define D     1024
#define DFF   4096
#define S_LEN 4096
#define NCHUNK 32
#define CHUNK  128

// Does this device-compilation pass have tcgen05 (arch-specific sm_100a/103a)?
#if defined(__CUDA_ARCH_FEAT_SM100_ALL) || defined(__CUDA_ARCH_FEAT_SM103_ALL) || \
    defined(__CUDA_ARCH_FEAT_SM101_ALL) || \
    (defined(__CUDA_ARCH_SPECIFIC__) && (__CUDA_ARCH_SPECIFIC__ >= 1000)) || \
    defined(__CUDA_ARCH_FAMILY_SPECIFIC__)
#define TC_PATH 1
#else
#define TC_PATH 0
#endif

// ---------------- scratch ----------------
__device__ __half g_h    [(size_t)MT * D];
__device__ __half g_Wgv  [(size_t)2 * D * D];
__device__ __half g_W1   [(size_t)DFF * D];
__device__ __half g_W2   [(size_t)D * DFF];
__device__ __half g_lin  [(size_t)MT * 2 * D];
__device__ __half g_gbuf [(size_t)MT * D];
__device__ __half g_gvbuf[(size_t)MT * D];
__device__ float  g_xmid [(size_t)MT * D];
__device__ __half g_h2   [(size_t)MT * D];
__device__ __half g_a1   [(size_t)MT * DFF];
__device__ float  g_pg   [4 * NCHUNK * D];
__device__ float  g_pv   [4 * NCHUNK * D];

// ---------------- helpers ----------------
__device__ __forceinline__ uint32_t smem_u32(const void* p) {
    return (uint32_t)__cvta_generic_to_shared(p);
}
__device__ __forceinline__ uint32_t swz(uint32_t off) {          // SW128: Swizzle<3,4,3>
    return off ^ ((off >> 3) & 0x70);
}
__device__ __forceinline__ void cp16(uint32_t dst, const void* src) {
    asm volatile("cp.async.cg.shared.global [%0], [%1], 16;\n" :: "r"(dst), "l"(src) : "memory");
}
__device__ __forceinline__ void cp_commit() { asm volatile("cp.async.commit_group;\n" ::: "memory"); }
__device__ __forceinline__ void cp_wait0()  { asm volatile("cp.async.wait_group 0;\n" ::: "memory"); }
__device__ __forceinline__ void cp_wait1()  { asm volatile("cp.async.wait_group 1;\n" ::: "memory"); }
__device__ __forceinline__ void cp_wait2()  { asm volatile("cp.async.wait_group 2;\n" ::: "memory"); }

__device__ __forceinline__ void ldsm4(uint32_t& r0, uint32_t& r1, uint32_t& r2, uint32_t& r3, uint32_t a) {
    asm volatile("ldmatrix.sync.aligned.m8n8.x4.shared.b16 {%0,%1,%2,%3}, [%4];\n"
                 : "=r"(r0), "=r"(r1), "=r"(r2), "=r"(r3) : "r"(a));
}
__device__ __forceinline__ void mma16816(float c[4],
                                         uint32_t a0, uint32_t a1, uint32_t a2, uint32_t a3,
                                         uint32_t b0, uint32_t b1) {
    asm volatile("mma.sync.aligned.m16n8k16.row.col.f32.f16.f16.f32 "
                 "{%0,%1,%2,%3},{%4,%5,%6,%7},{%8,%9},{%0,%1,%2,%3};\n"
                 : "+f"(c[0]), "+f"(c[1]), "+f"(c[2]), "+f"(c[3])
                 : "r"(a0), "r"(a1), "r"(a2), "r"(a3), "r"(b0), "r"(b1));
}
__device__ __forceinline__ float gelu_f(float x) {
    return 0.5f * x * (1.0f + erff(x * 0.70710678118654752f));
}

#if TC_PATH
__device__ __forceinline__ uint32_t elect_one_pred() {
    uint32_t pred;
    asm volatile("{\n\t.reg .pred p;\n\telect.sync _|p, 0xFFFFFFFF;\n\tselp.b32 %0, 1, 0, p;\n\t}"
                 : "=r"(pred));
    return pred;
}
__device__ __forceinline__ void mbar_init(uint32_t addr, uint32_t cnt) {
    asm volatile("mbarrier.init.shared.b64 [%0], %1;" :: "r"(addr), "r"(cnt) : "memory");
}
__device__ __forceinline__ void mbar_wait(uint32_t addr, uint32_t parity) {
    asm volatile(
        "{\n\t.reg .pred P;\n\t"
        "WAIT%=:\n\t"
        "mbarrier.try_wait.parity.acquire.cta.shared::cta.b64 P, [%0], %1, 0x989680;\n\t"
        "@P bra.uni DONE%=;\n\t"
        "bra.uni WAIT%=;\n\t"
        "DONE%=:\n\t}"
        :: "r"(addr), "r"(parity) : "memory");
}
__device__ __forceinline__ void tc_commit_mbar(uint32_t mbar) {
    asm volatile("tcgen05.commit.cta_group::1.mbarrier::arrive::one.shared::cluster.b64 [%0];"
                 :: "r"(mbar) : "memory");
}
__device__ __forceinline__ uint64_t make_desc_sw128(uint32_t addr) {
    return ((uint64_t)2 << 61) | ((uint64_t)1 << 46) | ((uint64_t)64 << 32) |
           ((uint64_t)1 << 16) | (((uint64_t)addr >> 4) & 0x3FFF);
}
__device__ __forceinline__ void mma_f16_ss(uint32_t d_tmem, uint64_t a_desc, uint64_t b_desc,
                                           uint32_t idesc, uint32_t en) {
    asm volatile(
        "{\n\t.reg .pred p;\n\t"
        "setp.ne.u32 p, %4, 0;\n\t"
        "tcgen05.mma.cta_group::1.kind::f16 [%0], %1, %2, %3, {%5, %5, %5, %5}, p;\n\t}"
        :: "r"(d_tmem), "l"(a_desc), "l"(b_desc), "r"(idesc), "r"(en), "r"(0u)
        : "memory");
}
__device__ __forceinline__ void tmem_ld32(uint32_t* r, uint32_t a) {
    asm volatile(
        "tcgen05.ld.sync.aligned.32x32b.x32.b32 "
        "{%0,%1,%2,%3,%4,%5,%6,%7,%8,%9,%10,%11,%12,%13,%14,%15,"
        "%16,%17,%18,%19,%20,%21,%22,%23,%24,%25,%26,%27,%28,%29,%30,%31}, [%32];"
        : "=r"(r[0]), "=r"(r[1]), "=r"(r[2]), "=r"(r[3]), "=r"(r[4]), "=r"(r[5]), "=r"(r[6]), "=r"(r[7]),
          "=r"(r[8]), "=r"(r[9]), "=r"(r[10]), "=r"(r[11]), "=r"(r[12]), "=r"(r[13]), "=r"(r[14]), "=r"(r[15]),
          "=r"(r[16]), "=r"(r[17]), "=r"(r[18]), "=r"(r[19]), "=r"(r[20]), "=r"(r[21]), "=r"(r[22]), "=r"(r[23]),
          "=r"(r[24]), "=r"(r[25]), "=r"(r[26]), "=r"(r[27]), "=r"(r[28]), "=r"(r[29]), "=r"(r[30]), "=r"(r[31])
        : "r"(a));
}
#endif  // TC_PATH

// ---------------- weight fp32 -> fp16 ----------------
__global__ void cvt_kernel(const float* __restrict__ src, __half* __restrict__ dst, int n4) {
    int i = blockIdx.x * blockDim.x + threadIdx.x;
    if (i >= n4) return;
    float4 v = ((const float4*)src)[i];
    ((__half2*)dst)[2 * i]     = __floats2half2_rn(v.x, v.y);
    ((__half2*)dst)[2 * i + 1] = __floats2half2_rn(v.z, v.w);
}

// ---------------- layernorm: one warp per row ----------------
__global__ void __launch_bounds__(256) ln_kernel(const float* __restrict__ in,
                                                 const float* __restrict__ w,
                                                 const float* __restrict__ b,
                                                 __half* __restrict__ out) {
    int row  = blockIdx.x * 8 + (threadIdx.x >> 5);
    int lane = threadIdx.x & 31;
    const float4* p = (const float4*)(in + (size_t)row * D);
    float4 v[8];
    float s = 0.f, sq = 0.f;
#pragma unroll
    for (int i = 0; i < 8; ++i) {
        v[i] = p[lane + i * 32];
        s  += v[i].x + v[i].y + v[i].z + v[i].w;
        sq += v[i].x * v[i].x + v[i].y * v[i].y + v[i].z * v[i].z + v[i].w * v[i].w;
    }
#pragma unroll
    for (int o = 16; o > 0; o >>= 1) {
        s  += __shfl_xor_sync(0xffffffffu, s, o);
        sq += __shfl_xor_sync(0xffffffffu, sq, o);
    }
    float mean = s * (1.0f / D);
    float inv  = rsqrtf(sq * (1.0f / D) - mean * mean + 1e-5f);
    __half2* o2 = (__half2*)(out + (size_t)row * D);
#pragma unroll
    for (int i = 0; i < 8; ++i) {
        int c4 = lane + i * 32;
        float4 wv = ((const float4*)w)[c4];
        float4 bv = ((const float4*)b)[c4];
        o2[c4 * 2]     = __floats2half2_rn((v[i].x - mean) * inv * wv.x + bv.x,
                                           (v[i].y - mean) * inv * wv.y + bv.y);
        o2[c4 * 2 + 1] = __floats2half2_rn((v[i].z - mean) * inv * wv.z + bv.z,
                                           (v[i].w - mean) * inv * wv.w + bv.w);
    }
}

// ---------------- g = sigmoid(gate+gb), gv = g*(val+vb) ----------------
__global__ void sigmul_kernel(const float* __restrict__ gate_b, const float* __restrict__ val_b) {
    int i  = blockIdx.x * blockDim.x + threadIdx.x;
    int m  = i >> 9;
    int c2 = i & 511;
    const __half2* lin2 = (const __half2*)g_lin;
    float2 gl = __half22float2(lin2[(size_t)m * 1024 + c2]);
    float2 vl = __half22float2(lin2[(size_t)m * 1024 + 512 + c2]);
    float2 gb = ((const float2*)gate_b)[c2];
    float2 vb = ((const float2*)val_b)[c2];
    float g0 = 1.0f / (1.0f + expf(-(gl.x + gb.x)));
    float g1 = 1.0f / (1.0f + expf(-(gl.y + gb.y)));
    ((__half2*)g_gbuf)[i]  = __floats2half2_rn(g0, g1);
    ((__half2*)g_gvbuf)[i] = __floats2half2_rn(g0 * (vl.x + vb.x), g1 * (vl.y + vb.y));
}

// ---------------- 3-phase blocked scan along S ----------------
__global__ void __launch_bounds__(256) scan1_kernel() {
    int d = blockIdx.x * 256 + threadIdx.x;
    int c = blockIdx.y, b = blockIdx.z;
    size_t base = ((size_t)b * S_LEN + (size_t)c * CHUNK) * D + d;
    float sg = 0.f, sv = 0.f;
#pragma unroll 4
    for (int s = 0; s < CHUNK; ++s) {
        sg += __half2float(g_gbuf [base + (size_t)s * D]);
        sv += __half2float(g_gvbuf[base + (size_t)s * D]);
    }
    g_pg[((size_t)b * NCHUNK + c) * D + d] = sg;
    g_pv[((size_t)b * NCHUNK + c) * D + d] = sv;
}
__global__ void __launch_bounds__(256) scan2_kernel() {
    int d = blockIdx.x * 256 + threadIdx.x;
    int b = blockIdx.y;
    float rg = 0.f, rv = 0.f;
    for (int c = 0; c < NCHUNK; ++c) {
        size_t i = ((size_t)b * NCHUNK + c) * D + d;
        float tg = g_pg[i], tv = g_pv[i];
        g_pg[i] = rg; g_pv[i] = rv;
        rg += tg; rv += tv;
    }
}
__global__ void __launch_bounds__(256) scan3_kernel(const float* __restrict__ x,
                                                    float* __restrict__ xmid) {
    int d = blockIdx.x * 256 + threadIdx.x;
    int c = blockIdx.y, b = blockIdx.z;
    float ag = g_pg[((size_t)b * NCHUNK + c) * D + d];
    float av = g_pv[((size_t)b * NCHUNK + c) * D + d];
    size_t base = ((size_t)b * S_LEN + (size_t)c * CHUNK) * D + d;
#pragma unroll 4
    for (int s0 = 0; s0 < CHUNK; ++s0) {
        size_t idx = base + (size_t)s0 * D;
        int s = c * CHUNK + s0;
        ag += __half2float(g_gbuf[idx]);
        av += __half2float(g_gvbuf[idx]);
        float scale = rsqrtf((ag + 1e-6f) * ((float)(s + 1) * (1.0f / S_LEN) + 0.1f));
        xmid[idx] = x[idx] + av * scale;
    }
}

// ---------------- GEMM: C[M,N] = A[M,K] * B[N,K]^T, CTA tile 128x256, K-tile 64 ----------------
// Stage layout (SW128 swizzled, shared by both paths): A 128x128B (16KB) then B 256x128B (32KB).
#define STAGE_BYTES 49152u
#define SMEM_DYN   (4 * 49152 + 1024)

__device__ __forceinline__ void load_stage(uint32_t sbase, int s,
                                           const __half* A, const __half* B,
                                           int K, int bm, int bn, int kt, int tid) {
    uint32_t sa = sbase + (uint32_t)s * STAGE_BYTES;
    uint32_t sb = sa + 16384u;
    const __half* gA = A + (size_t)bm * K + (size_t)kt * 64;
    const __half* gB = B + (size_t)bn * K + (size_t)kt * 64;
#pragma unroll
    for (int i = 0; i < 4; ++i) {               // A: 128 rows x 8 x 16B
        int id = tid + 256 * i;
        int r = id >> 3, c = id & 7;
        cp16(sa + swz((uint32_t)(r * 128 + c * 16)), gA + (size_t)r * K + c * 8);
    }
#pragma unroll
    for (int i = 0; i < 8; ++i) {               // B: 256 rows x 8 x 16B
        int id = tid + 256 * i;
        int r = id >> 3, c = id & 7;
        cp16(sb + swz((uint32_t)(r * 128 + c * 16)), gB + (size_t)r * K + c * 8);
    }
    cp_commit();
}

// EPI 0: raw fp16   EPI 1: gelu(acc+bias) fp16   EPI 2: acc+bias+resid fp32
template <int EPI>
__global__ void __launch_bounds__(256, 1) tc_gemm(const __half* __restrict__ A,
                                                  const __half* __restrict__ B,
                                                  int M, int N, int K,
                                                  const float* __restrict__ bias,
                                                  const float* __restrict__ resid,
                                                  __half* __restrict__ outH,
                                                  float* __restrict__ outF) {
    extern __shared__ char dsm[];
    const int tid  = threadIdx.x;
    const int warp = tid >> 5;
    const int lane = tid & 31;
    const int bm = blockIdx.y * 128;
    const int bn = blockIdx.x * 256;
    uint32_t sbase = (smem_u32(dsm) + 1023u) & ~1023u;
    const int KT = K >> 6;

#if TC_PATH
    // ================= tcgen05 path =================
    __shared__ __align__(16) uint32_t tslot[4];
    __shared__ __align__(8)  uint64_t mbars[4];
    uint32_t mb = smem_u32(mbars);

    if (warp == 0) {
        asm volatile("tcgen05.alloc.cta_group::1.sync.aligned.shared::cta.b32 [%0], %1;"
                     :: "r"(smem_u32(tslot)), "r"(256u) : "memory");
        asm volatile("tcgen05.relinquish_alloc_permit.cta_group::1.sync.aligned;");
    }
    if (tid == 0) {
        for (int s = 0; s < 4; ++s) mbar_init(mb + 8 * s, 1);
    }
    __syncthreads();
    uint32_t tmem;
    asm volatile("ld.shared.b32 %0, [%1];" : "=r"(tmem) : "r"(smem_u32(tslot)));

    const uint32_t idesc = (1u << 4) | (32u << 17) | (8u << 24);  // F32 acc, f16 ops, N=256, M=128

    load_stage(sbase, 0, A, B, K, bm, bn, 0, tid);
    load_stage(sbase, 1, A, B, K, bm, bn, 1, tid);
    load_stage(sbase, 2, A, B, K, bm, bn, 2, tid);

    for (int kt = 0; kt < KT; ++kt) {
        const int s = kt & 3;
        int pend = KT - 1 - kt; if (pend > 2) pend = 2;
        if (pend == 2) cp_wait2(); else if (pend == 1) cp_wait1(); else cp_wait0();
        asm volatile("fence.proxy.async.shared::cta;" ::: "memory");
        __syncthreads();

        if (warp == 0) {
            uint32_t sa = sbase + (uint32_t)s * STAGE_BYTES;
            uint64_t ad = make_desc_sw128(sa);
            uint64_t bd = make_desc_sw128(sa + 16384u);
            if (elect_one_pred()) {
#pragma unroll
                for (int kk = 0; kk < 4; ++kk)
                    mma_f16_ss(tmem, ad + 2 * kk, bd + 2 * kk, idesc, (kt | kk) != 0 ? 1u : 0u);
                tc_commit_mbar(mb + 8 * s);
            }
        }

        int lt = kt + 3;
        if (lt < KT) {
            if (kt >= 1) mbar_wait(mb + 8 * (lt & 3), ((kt - 1) >> 2) & 1);
            load_stage(sbase, lt & 3, A, B, K, bm, bn, lt, tid);
        }
    }

    mbar_wait(mb + 8 * ((KT - 1) & 3), ((KT - 1) >> 2) & 1);
    asm volatile("tcgen05.fence::after_thread_sync;" ::: "memory");

    const int row = bm + (warp & 3) * 32 + lane;
    const int colhalf = (warp >> 2) * 128;
#pragma unroll
    for (int cc = 0; cc < 4; ++cc) {
        int colbase = colhalf + cc * 32;
        uint32_t v[32];
        tmem_ld32(v, tmem + (uint32_t)colbase);
        asm volatile("tcgen05.wait::ld.sync.aligned;" ::: "memory");
        int col = bn + colbase;
        if (EPI == 0) {
            __half2 h2a[16];
#pragma unroll
            for (int c = 0; c < 16; ++c)
                h2a[c] = __floats2half2_rn(__uint_as_float(v[2 * c]), __uint_as_float(v[2 * c + 1]));
            uint4* dst = (uint4*)(outH + (size_t)row * N + col);
            const uint4* sp = (const uint4*)h2a;
#pragma unroll
            for (int q = 0; q < 4; ++q) dst[q] = sp[q];
        } else if (EPI == 1) {
            __half2 h2a[16];
#pragma unroll
            for (int c = 0; c < 16; ++c) {
                float a0 = __uint_as_float(v[2 * c])     + bias[col + 2 * c];
                float a1 = __uint_as_float(v[2 * c + 1]) + bias[col + 2 * c + 1];
                h2a[c] = __floats2half2_rn(gelu_f(a0), gelu_f(a1));
            }
            uint4* dst = (uint4*)(outH + (size_t)row * N + col);
            const uint4* sp = (const uint4*)h2a;
#pragma unroll
            for (int q = 0; q < 4; ++q) dst[q] = sp[q];
        } else {
            const float4* rp = (const float4*)(resid + (size_t)row * N + col);
            float4* op = (float4*)(outF + (size_t)row * N + col);
#pragma unroll
            for (int q = 0; q < 8; ++q) {
                float4 r4 = rp[q];
                float4 o;
                o.x = __uint_as_float(v[4 * q])     + bias[col + 4 * q]     + r4.x;
                o.y = __uint_as_float(v[4 * q + 1]) + bias[col + 4 * q + 1] + r4.y;
                o.z = __uint_as_float(v[4 * q + 2]) + bias[col + 4 * q + 2] + r4.z;
                o.w = __uint_as_float(v[4 * q + 3]) + bias[col + 4 * q + 3] + r4.w;
                op[q] = o;
            }
        }
    }

    __syncthreads();
    if (warp == 0) {
        asm volatile("tcgen05.dealloc.cta_group::1.sync.aligned.b32 %0, %1;"
                     :: "r"(tmem), "r"(256u));
    }
#else
    // ================= mma.sync fallback (plain sm_100) =================
    const int m0 = (warp >> 2) * 64;   // 2x4 warps, each 64x64
    const int n0 = (warp & 3) * 64;

    float acc[4][8][4];
#pragma unroll
    for (int i = 0; i < 4; ++i)
#pragma unroll
        for (int j = 0; j < 8; ++j)
#pragma unroll
            for (int q = 0; q < 4; ++q) acc[i][j][q] = 0.f;

    load_stage(sbase, 0, A, B, K, bm, bn, 0, tid);
    load_stage(sbase, 1, A, B, K, bm, bn, 1, tid);
    load_stage(sbase, 2, A, B, K, bm, bn, 2, tid);

    // per-lane ldmatrix address components (byte offsets within stage)
    const uint32_t aRow = (uint32_t)(m0 + (lane & 15));
    const uint32_t aColB = (uint32_t)((lane >> 4) * 16);
    const uint32_t bRow = (uint32_t)(n0 + ((lane >> 4) & 1) * 8 + (lane & 7));
    const uint32_t bColB = (uint32_t)(((lane >> 3) & 1) * 16);

    for (int kt = 0; kt < KT; ++kt) {
        const int s = kt & 3;
        int pend = KT - 1 - kt; if (pend > 2) pend = 2;
        if (pend == 2) cp_wait2(); else if (pend == 1) cp_wait1(); else cp_wait0();
        __syncthreads();

        int lt = kt + 3;
        if (lt < KT) load_stage(sbase, lt & 3, A, B, K, bm, bn, lt, tid);

        uint32_t sa = sbase + (uint32_t)s * STAGE_BYTES;
        uint32_t sb = sa + 16384u;
#pragma unroll
        for (int kk = 0; kk < 4; ++kk) {
            uint32_t a[4][4], bf[8][2];
#pragma unroll
            for (int mi = 0; mi < 4; ++mi)
                ldsm4(a[mi][0], a[mi][1], a[mi][2], a[mi][3],
                      sa + swz((aRow + mi * 16) * 128 + kk * 32 + aColB));
#pragma unroll
            for (int gi = 0; gi < 4; ++gi)
                ldsm4(bf[2 * gi][0], bf[2 * gi][1], bf[2 * gi + 1][0], bf[2 * gi + 1][1],
                      sb + swz((bRow + gi * 16) * 128 + kk * 32 + bColB));
#pragma unroll
            for (int mi = 0; mi < 4; ++mi)
#pragma unroll
                for (int ni = 0; ni < 8; ++ni)
                    mma16816(acc[mi][ni], a[mi][0], a[mi][1], a[mi][2], a[mi][3],
                             bf[ni][0], bf[ni][1]);
        }
        __syncthreads();
    }

#pragma unroll
    for (int mi = 0; mi < 4; ++mi) {
#pragma unroll
        for (int ni = 0; ni < 8; ++ni) {
            int row = bm + m0 + mi * 16 + (lane >> 2);
            int col = bn + n0 + ni * 8 + (lane & 3) * 2;
            float* ap = acc[mi][ni];
            if (EPI == 0) {
                *(__half2*)(outH + (size_t)row * N + col)       = __floats2half2_rn(ap[0], ap[1]);
                *(__half2*)(outH + (size_t)(row + 8) * N + col) = __floats2half2_rn(ap[2], ap[3]);
            } else if (EPI == 1) {
                float b0 = bias[col], b1 = bias[col + 1];
                *(__half2*)(outH + (size_t)row * N + col) =
                    __floats2half2_rn(gelu_f(ap[0] + b0), gelu_f(ap[1] + b1));
                *(__half2*)(outH + (size_t)(row + 8) * N + col) =
                    __floats2half2_rn(gelu_f(ap[2] + b0), gelu_f(ap[3] + b1));
            } else {
                float b0 = bias[col], b1 = bias[col + 1];
                float2 r0 = *(const float2*)(resid + (size_t)row * N + col);
                float2 r1 = *(const float2*)(resid + (size_t)(row + 8) * N + col);
                *(float2*)(outF + (size_t)row * N + col) =
                    make_float2(ap[0] + b0 + r0.x, ap[1] + b1 + r0.y);
                *(float2*)(outF + (size_t)(row + 8) * N + col) =
                    make_float2(ap[2] + b0 + r1.x, ap[3] + b1 + r1.y);
            }
        }
    }
#endif
}

// ---------------- launch ----------------
extern "C" void kernel_launch(void* const* d_in, const int* in_sizes, int n_in,
                              void* d_out, int out_size) {
    const float* x      = (const float*)d_in[0];
    const float* ln1_w  = (const float*)d_in[1];
    const float* ln1_b  = (const float*)d_in[2];
    const float* ln2_w  = (const float*)d_in[3];
    const float* ln2_b  = (const float*)d_in[4];
    const float* gate_w = (const float*)d_in[5];
    const float* gate_b = (const float*)d_in[6];
    const float* val_w  = (const float*)d_in[7];
    const float* val_b  = (const float*)d_in[8];
    const float* ffn1_w = (const float*)d_in[9];
    const float* ffn1_b = (const float*)d_in[10];
    const float* ffn2_w = (const float*)d_in[11];
    const float* ffn2_b = (const float*)d_in[12];
    float* out = (float*)d_out;

    void *pH, *pWgv, *pW1, *pW2, *pLin, *pXmid, *pH2, *pA1;
    cudaGetSymbolAddress(&pH,    g_h);
    cudaGetSymbolAddress(&pWgv,  g_Wgv);
    cudaGetSymbolAddress(&pW1,   g_W1);
    cudaGetSymbolAddress(&pW2,   g_W2);
    cudaGetSymbolAddress(&pLin,  g_lin);
    cudaGetSymbolAddress(&pXmid, g_xmid);
    cudaGetSymbolAddress(&pH2,   g_h2);
    cudaGetSymbolAddress(&pA1,   g_a1);

    cudaFuncSetAttribute(tc_gemm<0>, cudaFuncAttributeMaxDynamicSharedMemorySize, SMEM_DYN);
    cudaFuncSetAttribute(tc_gemm<1>, cudaFuncAttributeMaxDynamicSharedMemorySize, SMEM_DYN);
    cudaFuncSetAttribute(tc_gemm<2>, cudaFuncAttributeMaxDynamicSharedMemorySize, SMEM_DYN);

    // 1. weights fp32 -> fp16
    int n4a = D * D / 4;
    cvt_kernel<<<(n4a + 255) / 256, 256>>>(gate_w, (__half*)pWgv, n4a);
    cvt_kernel<<<(n4a + 255) / 256, 256>>>(val_w, (__half*)pWgv + (size_t)D * D, n4a);
    int n4f = DFF * D / 4;
    cvt_kernel<<<(n4f + 255) / 256, 256>>>(ffn1_w, (__half*)pW1, n4f);
    cvt_kernel<<<(n4f + 255) / 256, 256>>>(ffn2_w, (__half*)pW2, n4f);

    // 2. LN1
    ln_kernel<<<MT / 8, 256>>>(x, ln1_w, ln1_b, (__half*)pH);

    // 3. fused gate+val GEMM: [MT,1024] x [2048,1024]^T
    tc_gemm<0><<<dim3(2 * D / 256, MT / 128), 256, SMEM_DYN>>>(
        (const __half*)pH, (const __half*)pWgv, MT, 2 * D, D, nullptr, nullptr,
        (__half*)pLin, nullptr);

    // 4. sigmoid / gate*val
    sigmul_kernel<<<MT * 512 / 256, 256>>>(gate_b, val_b);

    // 5. blocked scan + memory + residual
    scan1_kernel<<<dim3(D / 256, NCHUNK, 4), 256>>>();
    scan2_kernel<<<dim3(D / 256, 4), 256>>>();
    scan3_kernel<<<dim3(D / 256, NCHUNK, 4), 256>>>(x, (float*)pXmid);

    // 6. LN2
    ln_kernel<<<MT / 8, 256>>>((const float*)pXmid, ln2_w, ln2_b, (__half*)pH2);

    // 7. FFN1 + gelu
    tc_gemm<1><<<dim3(DFF / 256, MT / 128), 256, SMEM_DYN>>>(
        (const __half*)pH2, (const __half*)pW1, MT, DFF, D, ffn1_b, nullptr,
        (__half*)pA1, nullptr);

    // 8. FFN2 + bias + residual
    tc_gemm<2><<<dim3(D / 256, MT / 128), 256, SMEM_DYN>>>(
        (const __half*)pA1, (const __half*)pW2, MT, D, DFF, ffn2_b, (const float*)pXmid,
        nullptr, out);
}